// round 9
// baseline (speedup 1.0000x reference)
#include <cuda_runtime.h>
#include <cuda_fp16.h>
#include <math.h>
#include <stdint.h>

#define BS_    128
#define SEQ    32
#define DIMN   512
#define P_     10
#define NTOP   6

#define KBIG   10000
#define KBIGP  10016            // padded to multiple of 32
#define KCONV  2560             // 512*5 (tap-major: k = tap*512 + din)
#define KPSL   1024

// ---------------- device scratch (no allocations allowed) -------------------
__device__ float  g_X  [BS_ * SEQ * DIMN];          // x fp32 (residual + tail)
__device__ __half g_Xh [BS_ * SEQ * DIMN];          // fp16(relu(x))
__device__ __half g_Y1h[BS_ * SEQ * DIMN];          // fp16(relu(y1))
__device__ float  g_psl[BS_ * 2 * P_ * DIMN];
__device__ float  g_P0 [BS_ * SEQ * DIMN];          // split-K partials
__device__ float  g_P1 [BS_ * SEQ * DIMN];

__device__ __half g_A  [(size_t)4096 * KBIGP];      // big activation buffer
__device__ __half g_Wc [(size_t)512 * KBIGP];
__device__ __half g_W1 [512 * KCONV];
__device__ __half g_W2 [512 * KCONV];
__device__ __half g_Wp [512 * KPSL];

// ---------------- ptx helpers -------------------------------------------------
__device__ __forceinline__ void cp16(uint32_t sa, const void* g) {
    asm volatile("cp.async.cg.shared.global [%0], [%1], 16;\n" :: "r"(sa), "l"(g) : "memory");
}
__device__ __forceinline__ void cp16z(uint32_t sa, const void* g, uint32_t srcsize) {
    asm volatile("cp.async.cg.shared.global [%0], [%1], 16, %2;\n"
                 :: "r"(sa), "l"(g), "r"(srcsize) : "memory");
}
__device__ __forceinline__ void cp_commit() {
    asm volatile("cp.async.commit_group;\n" ::: "memory");
}
template<int N> __device__ __forceinline__ void cp_wait() {
    asm volatile("cp.async.wait_group %0;\n" :: "n"(N) : "memory");
}
__device__ __forceinline__ uint32_t smem_u32(const void* p) {
    uint32_t a;
    asm("{ .reg .u64 t; cvta.to.shared.u64 t, %1; cvt.u32.u64 %0, t; }" : "=r"(a) : "l"(p));
    return a;
}
__device__ __forceinline__ void ldmx4(uint32_t* r, uint32_t addr) {
    asm volatile("ldmatrix.sync.aligned.m8n8.x4.shared.b16 {%0,%1,%2,%3}, [%4];"
                 : "=r"(r[0]), "=r"(r[1]), "=r"(r[2]), "=r"(r[3]) : "r"(addr));
}
__device__ __forceinline__ void mma_f16(float* d,
    uint32_t a0, uint32_t a1, uint32_t a2, uint32_t a3,
    uint32_t b0, uint32_t b1)
{
    asm volatile(
        "mma.sync.aligned.m16n8k16.row.col.f32.f16.f16.f32 "
        "{%0,%1,%2,%3}, {%4,%5,%6,%7}, {%8,%9}, {%0,%1,%2,%3};"
        : "+f"(d[0]), "+f"(d[1]), "+f"(d[2]), "+f"(d[3])
        : "r"(a0), "r"(a1), "r"(a2), "r"(a3), "r"(b0), "r"(b1));
}

// ---------------- conversion kernels -------------------------------------------
__global__ void __launch_bounds__(256) f32_to_f16_pad(
    const float* __restrict__ src, __half* __restrict__ dst, int K, int Kpad)
{
    const int row = blockIdx.y;
    const int c8  = (blockIdx.x * blockDim.x + threadIdx.x) << 3;
    if (c8 >= Kpad) return;
    const float* s = src + (size_t)row * K + c8;
    __half h[8];
    if (c8 + 8 <= K) {
        const float4 v0 = *(const float4*)s;
        const float4 v1 = *(const float4*)(s + 4);
        h[0] = __float2half(v0.x); h[1] = __float2half(v0.y);
        h[2] = __float2half(v0.z); h[3] = __float2half(v0.w);
        h[4] = __float2half(v1.x); h[5] = __float2half(v1.y);
        h[6] = __float2half(v1.z); h[7] = __float2half(v1.w);
    } else {
#pragma unroll
        for (int j = 0; j < 8; j++)
            h[j] = (c8 + j < K) ? __float2half(s[j]) : __float2half(0.f);
    }
    *(uint4*)(dst + (size_t)row * Kpad + c8) = *(const uint4*)h;
}

// both res weights (512, 512, 5) -> fp16 (512, 2560), k = tap*512 + din
__global__ void __launch_bounds__(256) reorder_w2_f16(
    const float* __restrict__ src1, __half* __restrict__ dst1,
    const float* __restrict__ src2, __half* __restrict__ dst2)
{
    int i = blockIdx.x * blockDim.x + threadIdx.x;
    const int n1 = 512 * KCONV;
    const float* src = (i < n1) ? src1 : src2;
    __half* dst = (i < n1) ? dst1 : dst2;
    int ii = (i < n1) ? i : i - n1;
    if (ii >= n1) return;
    int dout = ii / KCONV;
    int k    = ii - dout * KCONV;
    int tap  = k >> 9;
    int din  = k & 511;
    dst[ii] = __float2half(src[dout * KCONV + din * 5 + tap]);
}

// concat(obj, motion) -> fp16 (2560, 1024)
__global__ void __launch_bounds__(256) concat_f16(
    const float* __restrict__ obj, const float* __restrict__ motion,
    __half* __restrict__ A)
{
    int i = blockIdx.x * blockDim.x + threadIdx.x;      // 2560*128
    if (i >= 2560 * 128) return;
    int row = i >> 7;
    int c8  = (i & 127) << 3;
    int b = row / 20, p = row - b * 20;
    const float* s = (p < P_) ? obj    + ((size_t)(b * P_ + p      )) * 1024 + c8
                              : motion + ((size_t)(b * P_ + p - P_ )) * 1024 + c8;
    const float4 v0 = *(const float4*)s;
    const float4 v1 = *(const float4*)(s + 4);
    __half h[8];
    h[0] = __float2half(v0.x); h[1] = __float2half(v0.y);
    h[2] = __float2half(v0.z); h[3] = __float2half(v0.w);
    h[4] = __float2half(v1.x); h[5] = __float2half(v1.y);
    h[6] = __float2half(v1.z); h[7] = __float2half(v1.w);
    *(uint4*)(A + (size_t)row * KPSL + c8) = *(const uint4*)h;
}

// ---------------- split-K combine: v = P0+P1+bias ------------------------------
// MODE 1: X=v, Xh=h(relu(v)) | MODE 2: Y1h=h(relu(v)) | MODE 3: X += 0.3*v
template<int MODE>
__global__ void __launch_bounds__(256) combine_k(
    const float* __restrict__ P0, const float* __restrict__ P1,
    const float* __restrict__ bias, float* __restrict__ X, __half* __restrict__ H)
{
    const int i = blockIdx.x * blockDim.x + threadIdx.x;   // over 4096*128 float4s
    if (i >= BS_ * SEQ * DIMN / 4) return;
    const int c4 = (i & 127) << 2;
    const float4 p0 = *(const float4*)(P0 + (size_t)i * 4);
    const float4 p1 = *(const float4*)(P1 + (size_t)i * 4);
    const float4 bb = *(const float4*)(bias + c4);
    float4 v;
    v.x = p0.x + p1.x + bb.x;  v.y = p0.y + p1.y + bb.y;
    v.z = p0.z + p1.z + bb.z;  v.w = p0.w + p1.w + bb.w;
    if (MODE == 1) *(float4*)(X + (size_t)i * 4) = v;
    if (MODE == 3) {
        float4 o = *(const float4*)(X + (size_t)i * 4);
        o.x += 0.3f * v.x; o.y += 0.3f * v.y; o.z += 0.3f * v.z; o.w += 0.3f * v.w;
        *(float4*)(X + (size_t)i * 4) = o;
    }
    if (MODE == 1 || MODE == 2) {
        __half h[4];
        h[0] = __float2half(fmaxf(v.x, 0.f));
        h[1] = __float2half(fmaxf(v.y, 0.f));
        h[2] = __float2half(fmaxf(v.z, 0.f));
        h[3] = __float2half(fmaxf(v.w, 0.f));
        *(uint2*)(H + (size_t)i * 4) = *(const uint2*)h;
    }
}

// ---------------- mma.sync GEMM, 4-stage cp.async + ldmatrix -------------------
// CTA tile 128(M) x 64(N), BK=32, 128 thr (2x2 warps, warp tile 64x32).
// EPI 0: C=acc+bias (single-K)  |  EPI 4: raw partial store, split-K via blockIdx.z
#define TILEN   64
#define MATA    10240u                 // 128 rows x 80 B
#define MATBB   5120u                  // 64 rows x 80 B
#define STAGEB  (MATA + MATBB)         // 15360
#define NSTAGE  4

template<int AMODE>
__device__ __forceinline__ void load_stage(
    uint32_t sb, int t,
    const __half* __restrict__ A, const __half* __restrict__ B,
    int row0, int col0, int K, int k0)
{
#pragma unroll
    for (int j = 0; j < 4; j++) {
        const int cid = j * 128 + t;
        const int r  = cid >> 2, ch = cid & 3;
        const uint32_t sa = sb + (uint32_t)(r * 80 + ch * 16);
        if (AMODE == 0) {
            cp16(sa, A + (size_t)(row0 + r) * K + k0 + ch * 8);
        } else {
            const int grow = row0 + r;
            const int tap  = k0 >> 9;
            const int din0 = (k0 & 511) + ch * 8;
            const int s2   = (grow & 31) + tap - 2;
            const uint32_t ok = (s2 >= 0 && s2 < SEQ) ? 16u : 0u;
            const int srow = ok ? (grow + tap - 2) : grow;
            cp16z(sa, A + (size_t)srow * DIMN + din0, ok);
        }
    }
#pragma unroll
    for (int j = 0; j < 2; j++) {
        const int cid = j * 128 + t;
        const int r  = cid >> 2, ch = cid & 3;
        cp16(sb + MATA + (uint32_t)(r * 80 + ch * 16),
             B + (size_t)(col0 + r) * K + k0 + ch * 8);
    }
}

template<int AMODE, int EPI>
__global__ void __launch_bounds__(128, 3) gemm_mma(
    const __half* __restrict__ A, const __half* __restrict__ B,
    const float* __restrict__ bias, float* __restrict__ C0,
    float* __restrict__ C1, __half* __restrict__ H, int K)
{
    extern __shared__ char smem[];
    const uint32_t sbase = smem_u32(smem);
    const int t = threadIdx.x;
    const int wid = t >> 5, lane = t & 31;
    const int warp_m = wid >> 1, warp_n = wid & 1;
    const int tr = lane >> 2, tc = lane & 3;
    const int row0 = blockIdx.y * 128;
    const int col0 = blockIdx.x * TILEN;

    const int nch_tot = K >> 5;
    int kbase = 0, nch = nch_tot;
    float* Cout = C0;
    if (EPI == 4) {
        const int half0 = (nch_tot + 1) >> 1;
        if (blockIdx.z == 0) { nch = half0; }
        else                 { nch = nch_tot - half0; kbase = half0 * 32; Cout = C1; }
    }

    const uint32_t a_off = (uint32_t)((warp_m * 64 + (lane & 15)) * 80 + (lane >> 4) * 16);
    const uint32_t b_off = MATA +
        (uint32_t)((warp_n * 32 + (lane & 7) + ((lane >> 4) << 3)) * 80 + ((lane >> 3) & 1) * 16);

    float acc[4][4][4];
#pragma unroll
    for (int i = 0; i < 4; i++)
#pragma unroll
        for (int j = 0; j < 4; j++)
#pragma unroll
            for (int e = 0; e < 4; e++) acc[i][j][e] = 0.f;

#pragma unroll
    for (int s = 0; s < NSTAGE - 1; s++) {
        if (s < nch)
            load_stage<AMODE>(sbase + s * STAGEB, t, A, B, row0, col0, K, kbase + s * 32);
        cp_commit();
    }

    for (int i = 0; i < nch; i++) {
        cp_wait<NSTAGE - 2>();
        __syncthreads();

        if (i + NSTAGE - 1 < nch)
            load_stage<AMODE>(sbase + ((i + NSTAGE - 1) & (NSTAGE - 1)) * STAGEB,
                              t, A, B, row0, col0, K, kbase + (i + NSTAGE - 1) * 32);
        cp_commit();

        const uint32_t sb = sbase + (uint32_t)(i & (NSTAGE - 1)) * STAGEB;
#pragma unroll
        for (int k16 = 0; k16 < 2; k16++) {
            uint32_t a[4][4], b[4][2];
#pragma unroll
            for (int mt = 0; mt < 4; mt++)
                ldmx4(a[mt], sb + a_off + (uint32_t)(mt * 1280 + k16 * 32));
#pragma unroll
            for (int j = 0; j < 2; j++) {
                uint32_t r[4];
                ldmx4(r, sb + b_off + (uint32_t)(j * 1280 + k16 * 32));
                b[2 * j][0] = r[0]; b[2 * j][1] = r[1];
                b[2 * j + 1][0] = r[2]; b[2 * j + 1][1] = r[3];
            }
#pragma unroll
            for (int mt = 0; mt < 4; mt++)
#pragma unroll
                for (int nt = 0; nt < 4; nt++)
                    mma_f16(acc[mt][nt], a[mt][0], a[mt][1], a[mt][2], a[mt][3],
                            b[nt][0], b[nt][1]);
        }
    }

    // epilogue
#pragma unroll
    for (int mt = 0; mt < 4; mt++) {
        const int r0 = row0 + warp_m * 64 + mt * 16 + tr;
#pragma unroll
        for (int nt = 0; nt < 4; nt++) {
            const int cc = col0 + warp_n * 32 + nt * 8 + tc * 2;
            float* p0 = Cout + (size_t)r0 * DIMN + cc;
            float* p1 = Cout + (size_t)(r0 + 8) * DIMN + cc;
            if (EPI == 4) {
                *(float2*)p0 = make_float2(acc[mt][nt][0], acc[mt][nt][1]);
                *(float2*)p1 = make_float2(acc[mt][nt][2], acc[mt][nt][3]);
            } else {
                const float bx = __ldg(bias + cc), by = __ldg(bias + cc + 1);
                *(float2*)p0 = make_float2(acc[mt][nt][0] + bx, acc[mt][nt][1] + by);
                *(float2*)p1 = make_float2(acc[mt][nt][2] + bx, acc[mt][nt][3] + by);
            }
        }
    }
}

// ---------------- per-batch tail ------------------------------------------------
__global__ void __launch_bounds__(256) final_kernel(
    const float* __restrict__ alpha_all,  // (128, 32, 20)
    const float* __restrict__ att_mask,   // (128, 1, 32)
    const float* __restrict__ ln_g, const float* __restrict__ ln_b,
    const float* __restrict__ sv_w, const float* __restrict__ sv_b,
    const float* __restrict__ ss_w, const float* __restrict__ ss_b,
    const float* __restrict__ cl_w, const float* __restrict__ cl_b,
    float* __restrict__ out)              // (128, 6)
{
    const int b    = blockIdx.x;
    const int t    = threadIdx.x;
    const int warp = t >> 5;
    const int lane = t & 31;

    __shared__ float spt [NTOP][DIMN];
    __shared__ float sagg[NTOP][DIMN];
    __shared__ float sc  [NTOP][DIMN];
    __shared__ float adj [SEQ][NTOP];
    __shared__ float sums[20];
    __shared__ int   idxs[NTOP];
    __shared__ float smask[SEQ];

    if (t < SEQ) smask[t] = att_mask[b * SEQ + t];
    __syncthreads();

    if (t < 20) {
        float s = 0.f;
        for (int si = 0; si < SEQ; si++)
            s = fmaf(alpha_all[((size_t)b * SEQ + si) * 20 + t], smask[si], s);
        sums[t] = s;
    }
    __syncthreads();

    if (t == 0) {   // lax.top_k: descending, first index on ties
        unsigned used = 0;
        for (int k = 0; k < NTOP; k++) {
            int best = 0; float bv = -3.4e38f;
            for (int p = 0; p < 20; p++)
                if (!((used >> p) & 1u) && sums[p] > bv) { bv = sums[p]; best = p; }
            used |= (1u << best);
            idxs[k] = best;
        }
    }
    __syncthreads();

    for (int i = t; i < NTOP * DIMN; i += 256) {
        const int k = i >> 9, d = i & 511;
        spt[k][d] = g_psl[((size_t)b * 20 + idxs[k]) * DIMN + d];
    }
    __syncthreads();

    for (int pair = warp; pair < SEQ * NTOP; pair += 8) {
        const int s = pair / NTOP;
        const int k = pair - s * NTOP;
        const float* xr = g_X + ((size_t)b * SEQ + s) * DIMN;
        float acc = 0.f;
        for (int d = lane; d < DIMN; d += 32)
            acc = fmaf(xr[d], spt[k][d], acc);
#pragma unroll
        for (int o = 16; o > 0; o >>= 1)
            acc += __shfl_down_sync(0xffffffffu, acc, o);
        if (lane == 0) {
            const float v = acc * 0.04419417382415922f;
            adj[s][k] = (smask[s] > 0.f) ? v : -9.0e15f;
        }
    }
    __syncthreads();

    if (warp < NTOP) {
        const int k = warp;
        float v = adj[lane][k];
        float m = v;
#pragma unroll
        for (int o = 16; o > 0; o >>= 1)
            m = fmaxf(m, __shfl_xor_sync(0xffffffffu, m, o));
        const float e = expf(v - m);
        float ss = e;
#pragma unroll
        for (int o = 16; o > 0; o >>= 1)
            ss += __shfl_xor_sync(0xffffffffu, ss, o);
        adj[lane][k] = e / ss;
    }
    __syncthreads();

    for (int d = t; d < DIMN; d += 256) {
        float a[NTOP];
#pragma unroll
        for (int k = 0; k < NTOP; k++) a[k] = 0.f;
        for (int s = 0; s < SEQ; s++) {
            const float xv = g_X[((size_t)b * SEQ + s) * DIMN + d];
#pragma unroll
            for (int k = 0; k < NTOP; k++) a[k] = fmaf(xv, adj[s][k], a[k]);
        }
#pragma unroll
        for (int k = 0; k < NTOP; k++) sagg[k][d] = a[k];
    }
    __syncthreads();

    if (warp < NTOP) {
        const int k = warp;
        float sum = 0.f, sq = 0.f;
        for (int d = lane; d < DIMN; d += 32) {
            const float v = sagg[k][d];
            sum += v;
            sq = fmaf(v, v, sq);
        }
#pragma unroll
        for (int o = 16; o > 0; o >>= 1) {
            sum += __shfl_xor_sync(0xffffffffu, sum, o);
            sq  += __shfl_xor_sync(0xffffffffu, sq,  o);
        }
        const float mu  = sum * (1.f / DIMN);
        const float var = sq * (1.f / DIMN) - mu * mu;
        const float inv = rsqrtf(var + 1e-5f);
        for (int d = lane; d < DIMN; d += 32)
            sagg[k][d] = (sagg[k][d] - mu) * inv * ln_g[d] + ln_b[d];
    }
    __syncthreads();

    // v/s GEMVs, d-major: each weight row read once, all 6 k in registers.
    {
        const int d = t * 2;
        float accv[2][NTOP], accs[2][NTOP];
#pragma unroll
        for (int j = 0; j < 2; j++)
#pragma unroll
            for (int k = 0; k < NTOP; k++) {
                accv[j][k] = sv_b[d + j];
                accs[j][k] = ss_b[d + j];
            }
        const float4* wv0 = (const float4*)(sv_w + (size_t)d * DIMN);
        const float4* wv1 = (const float4*)(sv_w + (size_t)(d + 1) * DIMN);
        const float4* ws0 = (const float4*)(ss_w + (size_t)d * DIMN);
        const float4* ws1 = (const float4*)(ss_w + (size_t)(d + 1) * DIMN);
#pragma unroll 2
        for (int e = 0; e < DIMN / 4; e++) {
            const float4 v0 = wv0[e], v1 = wv1[e];
            const float4 s0 = ws0[e], s1 = ws1[e];
#pragma unroll
            for (int k = 0; k < NTOP; k++) {
                const float4 a = *(const float4*)(&spt[k][e * 4]);
                const float4 g = *(const float4*)(&sagg[k][e * 4]);
                accv[0][k] = fmaf(a.x, v0.x, fmaf(a.y, v0.y, fmaf(a.z, v0.z, fmaf(a.w, v0.w, accv[0][k]))));
                accv[1][k] = fmaf(a.x, v1.x, fmaf(a.y, v1.y, fmaf(a.z, v1.z, fmaf(a.w, v1.w, accv[1][k]))));
                accs[0][k] = fmaf(g.x, s0.x, fmaf(g.y, s0.y, fmaf(g.z, s0.z, fmaf(g.w, s0.w, accs[0][k]))));
                accs[1][k] = fmaf(g.x, s1.x, fmaf(g.y, s1.y, fmaf(g.z, s1.z, fmaf(g.w, s1.w, accs[1][k]))));
            }
        }
#pragma unroll
        for (int j = 0; j < 2; j++) {
            const float cw = cl_w[d + j];
#pragma unroll
            for (int k = 0; k < NTOP; k++)
                sc[k][d + j] = tanhf(accv[j][k]) * tanhf(accs[j][k]) * cw;
        }
    }
    __syncthreads();

    if (warp < NTOP) {
        const int k = warp;
        float s = 0.f;
        for (int d = lane; d < DIMN; d += 32) s += sc[k][d];
#pragma unroll
        for (int o = 16; o > 0; o >>= 1)
            s += __shfl_xor_sync(0xffffffffu, s, o);
        if (lane == 0) {
            const float z = s + cl_b[0];
            out[b * NTOP + k] = 1.f / (1.f + expf(-z));
        }
    }
}

// ---------------- launch ----------------------------------------------------------
extern "C" void kernel_launch(void* const* d_in, const int* in_sizes, int n_in,
                              void* d_out, int out_size)
{
    const float* inputs   = (const float*)d_in[0];
    const float* obj      = (const float*)d_in[2];
    const float* motion   = (const float*)d_in[3];
    const float* att_mask = (const float*)d_in[4];
    const float* alpha    = (const float*)d_in[5];
    const float* conv_w   = (const float*)d_in[6];
    const float* conv_b   = (const float*)d_in[7];
    const float* res_w1   = (const float*)d_in[8];
    const float* res_b1   = (const float*)d_in[9];
    const float* res_w2   = (const float*)d_in[10];
    const float* res_b2   = (const float*)d_in[11];
    const float* psl_w    = (const float*)d_in[12];
    const float* psl_b    = (const float*)d_in[13];
    const float* ln_g     = (const float*)d_in[14];
    const float* ln_b     = (const float*)d_in[15];
    const float* sv_w     = (const float*)d_in[16];
    const float* sv_b     = (const float*)d_in[17];
    const float* ss_w     = (const float*)d_in[18];
    const float* ss_b     = (const float*)d_in[19];
    const float* cl_w     = (const float*)d_in[20];
    const float* cl_b     = (const float*)d_in[21];
    float* out = (float*)d_out;

    float *X, *PSL, *P0, *P1;
    __half *Xh, *Y1h, *A, *Wc, *W1, *W2, *Wp;
    cudaGetSymbolAddress((void**)&X,   g_X);
    cudaGetSymbolAddress((void**)&Xh,  g_Xh);
    cudaGetSymbolAddress((void**)&Y1h, g_Y1h);
    cudaGetSymbolAddress((void**)&PSL, g_psl);
    cudaGetSymbolAddress((void**)&P0,  g_P0);
    cudaGetSymbolAddress((void**)&P1,  g_P1);
    cudaGetSymbolAddress((void**)&A,   g_A);
    cudaGetSymbolAddress((void**)&Wc,  g_Wc);
    cudaGetSymbolAddress((void**)&W1,  g_W1);
    cudaGetSymbolAddress((void**)&W2,  g_W2);
    cudaGetSymbolAddress((void**)&Wp,  g_Wp);

    const int SMEM_BYTES = NSTAGE * (int)STAGEB;   // 61440
    cudaFuncSetAttribute(gemm_mma<0,4>, cudaFuncAttributeMaxDynamicSharedMemorySize, SMEM_BYTES);
    cudaFuncSetAttribute(gemm_mma<1,4>, cudaFuncAttributeMaxDynamicSharedMemorySize, SMEM_BYTES);
    cudaFuncSetAttribute(gemm_mma<0,0>, cudaFuncAttributeMaxDynamicSharedMemorySize, SMEM_BYTES);

    const dim3 blk(128);
    const dim3 gBigS(DIMN / TILEN, 32, 2);  // (8, 32, 2) = 512 CTAs (split-K)
    const dim3 gPsl(DIMN / TILEN, 20, 1);   // (8, 20) = 160 CTAs
    const int  nComb = (BS_ * SEQ * DIMN / 4 + 255) / 256;

    // #0..#2: conversions
    f32_to_f16_pad<<<dim3((KBIGP / 8 + 255) / 256, 4096), 256>>>(inputs, A, KBIG, KBIGP);
    f32_to_f16_pad<<<dim3((KBIGP / 8 + 255) / 256, 512),  256>>>(conv_w, Wc, KBIG, KBIGP);
    reorder_w2_f16<<<(2 * 512 * KCONV + 255) / 256, 256>>>(res_w1, W1, res_w2, W2);

    // #3: GEMM1 split-K (profiled slot) -> P0/P1; #4: combine -> X, Xh
    gemm_mma<0, 4><<<gBigS, blk, SMEM_BYTES>>>(A, Wc, conv_b, P0, P1, Xh, KBIGP);
    combine_k<1><<<nComb, 256>>>(P0, P1, conv_b, X, Xh);

    // #5/#6: GEMM2 split-K (fused im2col) -> combine -> Y1h
    gemm_mma<1, 4><<<gBigS, blk, SMEM_BYTES>>>(Xh, W1, res_b1, P0, P1, Y1h, KCONV);
    combine_k<2><<<nComb, 256>>>(P0, P1, res_b1, X, Y1h);

    // #7/#8: GEMM3 split-K (fused im2col) -> combine -> X += 0.3*(...)
    gemm_mma<1, 4><<<gBigS, blk, SMEM_BYTES>>>(Y1h, W2, res_b2, P0, P1, Xh, KCONV);
    combine_k<3><<<nComb, 256>>>(P0, P1, res_b2, X, Xh);

    // #9..#11: psl path
    f32_to_f16_pad<<<dim3((KPSL / 8 + 255) / 256, 512), 256>>>(psl_w, Wp, KPSL, KPSL);
    concat_f16<<<(2560 * 128 + 255) / 256, 256>>>(obj, motion, A);
    gemm_mma<0, 0><<<gPsl, blk, SMEM_BYTES>>>(A, Wp, psl_b, PSL, P1 /*unused*/, Xh /*unused*/, KPSL);

    // #12: tail
    final_kernel<<<BS_, 256>>>(alpha, att_mask, ln_g, ln_b,
                               sv_w, sv_b, ss_w, ss_b, cl_w, cl_b, out);
}